// round 3
// baseline (speedup 1.0000x reference)
#include <cuda_runtime.h>

#define NN 262144
#define DD 128
#define KK 512
#define GG 4096
#define TT 10

// output layout (float32, concatenated reference tuple)
#define OFF_CPRE   0
#define OFF_XPRE   (GG * TT)            // counter_pre
#define OFF_YPRE   (2 * GG * TT)
#define OFF_Z      (3 * GG * TT)
#define OFF_PCA    (OFF_Z + (size_t)NN * DD)
#define OFF_PX     (OFF_PCA + (size_t)GG * DD)

#define MARGIN_THRESH 0.05f

__device__ int   g_idx[NN];
__device__ int   g_seg[GG + 1];
__device__ float g_c2[KK];       // fast-path c2
__device__ float g_c2e[KK];      // reference-emulated c2 (sequential fp32, no fma)
__device__ int   g_flag[NN];
__device__ int   g_nflag;

// ---------------- segment offsets via binary search (batch is sorted) ----------------
__global__ void seg_kernel(const int* __restrict__ bw, int n) {
    int g = blockIdx.x * blockDim.x + threadIdx.x;
    if (g == 0) g_nflag = 0;
    if (g > GG) return;
    // int64 little-endian: high words zero. int32 sorted batch: last word ~4095.
    bool is64 = (bw[n - 1] == 0) && (bw[n - 3] == 0);
    int lo = 0, hi = n;
    while (lo < hi) {
        int mid = (lo + hi) >> 1;
        int v = is64 ? bw[2 * mid] : bw[mid];
        if (v < g) lo = mid + 1; else hi = mid;
    }
    g_seg[g] = lo;
}

// ---------------- fast squared norms (for GEMM epilogue) ----------------
__global__ void c2_kernel(const float* __restrict__ cc) {
    int k = blockIdx.x * 8 + (threadIdx.x >> 5);
    int lane = threadIdx.x & 31;
    float s = 0.f;
#pragma unroll
    for (int j = 0; j < 4; ++j) {
        float v = cc[k * DD + lane + 32 * j];
        s = fmaf(v, v, s);
    }
#pragma unroll
    for (int o = 16; o; o >>= 1) s += __shfl_xor_sync(0xffffffffu, s, o);
    if (lane == 0) g_c2[k] = s;
}

// ---------------- reference-emulated c2: strict sequential fp32, mul+add, no fma ------
__global__ void c2emul_kernel(const float* __restrict__ cc) {
    int k = blockIdx.x * 128 + threadIdx.x;
    if (k >= KK) return;
    const float* r = cc + (size_t)k * DD;
    float acc = 0.f;
    for (int d = 0; d < DD; ++d)
        acc = __fadd_rn(acc, __fmul_rn(r[d], r[d]));
    g_c2e[k] = acc;
}

// ---------------- argmin_k (c2[k] - 2 x.c_k) : tiled fp32 GEMM + margin flag ----------
// block: 64 nodes x all 512 codes, 256 threads, per-thread 4 nodes x 8 codes.
__global__ __launch_bounds__(256) void argmin_kernel(
    const float* __restrict__ x, const float* __restrict__ cb)
{
    __shared__ float xs[DD][64];        // 32 KB, transposed: xs[d][n]
    __shared__ float cs[2][128][16];    // 16 KB, cs[buf][code][d_in_chunk]

    const int tid = threadIdx.x;
    const int tx = tid & 15;            // node group: nodes 4*tx .. 4*tx+3
    const int ty = tid >> 4;            // code group: codes 8*ty .. 8*ty+7 (in 128-tile)
    const int nbase = blockIdx.x * 64;
    const float4* x4  = (const float4*)x;
    const float4* cb4 = (const float4*)cb;

    {
        int n  = tid & 63;
        int q0 = tid >> 6;              // 0..3
#pragma unroll
        for (int j = 0; j < 8; ++j) {
            int q = q0 + 4 * j;
            float4 v = x4[(size_t)(nbase + n) * 32 + q];
            xs[4 * q + 0][n] = v.x;
            xs[4 * q + 1][n] = v.y;
            xs[4 * q + 2][n] = v.z;
            xs[4 * q + 3][n] = v.w;
        }
    }

    float bestv[4], bestv2[4];
    int   besti[4];
#pragma unroll
    for (int j = 0; j < 4; ++j) { bestv[j] = 3.4e38f; bestv2[j] = 3.4e38f; besti[j] = 0; }

    for (int kt = 0; kt < 4; ++kt) {            // 4 code tiles of 128
        float acc[4][8];
#pragma unroll
        for (int j = 0; j < 4; ++j)
#pragma unroll
            for (int i = 0; i < 8; ++i) acc[j][i] = 0.f;

#pragma unroll
        for (int j = 0; j < 2; ++j) {
            int ff = tid + 256 * j;
            int c = ff >> 2, q = ff & 3;
            float4 v = cb4[(size_t)(kt * 128 + c) * 32 + q];
            *(float4*)&cs[0][c][4 * q] = v;
        }
        __syncthreads();

        for (int dc = 0; dc < 8; ++dc) {        // 8 d-chunks of 16
            int cur = dc & 1, nxt = cur ^ 1;
            float4 pre[2];
            if (dc < 7) {
#pragma unroll
                for (int j = 0; j < 2; ++j) {
                    int ff = tid + 256 * j;
                    int c = ff >> 2, q = ff & 3;
                    pre[j] = cb4[(size_t)(kt * 128 + c) * 32 + (dc + 1) * 4 + q];
                }
            }
#pragma unroll
            for (int dd = 0; dd < 16; ++dd) {
                float4 a = *(const float4*)&xs[dc * 16 + dd][4 * tx];
                float b[8];
#pragma unroll
                for (int i = 0; i < 8; ++i) b[i] = cs[cur][8 * ty + i][dd];
#pragma unroll
                for (int i = 0; i < 8; ++i) {
                    acc[0][i] = fmaf(a.x, b[i], acc[0][i]);
                    acc[1][i] = fmaf(a.y, b[i], acc[1][i]);
                    acc[2][i] = fmaf(a.z, b[i], acc[2][i]);
                    acc[3][i] = fmaf(a.w, b[i], acc[3][i]);
                }
            }
            if (dc < 7) {
#pragma unroll
                for (int j = 0; j < 2; ++j) {
                    int ff = tid + 256 * j;
                    int c = ff >> 2, q = ff & 3;
                    *(float4*)&cs[nxt][c][4 * q] = pre[j];
                }
            }
            __syncthreads();
        }

        // epilogue: score = c2 - 2*dot, keep top-2 (k ascending => first-min kept)
#pragma unroll
        for (int i = 0; i < 8; ++i) {
            int k = kt * 128 + 8 * ty + i;
            float c2v = g_c2[k];
#pragma unroll
            for (int j = 0; j < 4; ++j) {
                float s = fmaf(-2.f, acc[j][i], c2v);
                if (s < bestv[j]) { bestv2[j] = bestv[j]; bestv[j] = s; besti[j] = k; }
                else if (s < bestv2[j]) bestv2[j] = s;
            }
        }
    }

    // cross-thread top-2 reduction over the 16 code groups (overlay scratch)
    float (*rv )[64] = (float(*)[64])&cs[0][0][0];   // best val, 16x64
    int   (*ri )[64] = (int  (*)[64])&cs[0][64][0];  // best idx, 16x64
    float (*rv2)[64] = (float(*)[64])&cs[1][0][0];   // 2nd val,  16x64
#pragma unroll
    for (int j = 0; j < 4; ++j) {
        rv [ty][4 * tx + j] = bestv[j];
        ri [ty][4 * tx + j] = besti[j];
        rv2[ty][4 * tx + j] = bestv2[j];
    }
    __syncthreads();
    if (tid < 64) {
        float bv = 3.4e38f, bv2 = 3.4e38f; int bi = 0x7fffffff;
#pragma unroll
        for (int t = 0; t < 16; ++t) {
            float v1 = rv[t][tid], v2 = rv2[t][tid];
            int   k1 = ri[t][tid];
            if (v1 < bv || (v1 == bv && k1 < bi)) {
                bv2 = fminf(bv, v2); bv = v1; bi = k1;
            } else {
                bv2 = fminf(bv2, v1);
            }
        }
        int node = nbase + tid;
        g_idx[node] = bi;
        if (bv2 - bv < MARGIN_THRESH) {
            int pos = atomicAdd(&g_nflag, 1);
            g_flag[pos] = node;
        }
    }
}

// ---------------- near-tie refine: bit-emulate the reference's fp32 arithmetic --------
// d2_ref[k] = fadd(x2, c2e[k]) - 2*dot, dot = k-ascending fmaf chain (Eigen gebp /
// cublas sgemm accumulation), x2/c2e = strict sequential mul+add (XLA reduce, no fma).
__global__ __launch_bounds__(128) void refine_kernel(
    const float* __restrict__ x, const float* __restrict__ cb)
{
    __shared__ float xsh[DD];
    __shared__ float x2sh;
    __shared__ float bvs[128];
    __shared__ int   bis[128];
    const int tid = threadIdx.x;
    const int nflag = g_nflag;

    for (int f = blockIdx.x; f < nflag; f += gridDim.x) {
        int node = g_flag[f];
        xsh[tid] = x[(size_t)node * DD + tid];
        __syncthreads();
        if (tid == 0) {
            float acc = 0.f;
            for (int d = 0; d < DD; ++d)
                acc = __fadd_rn(acc, __fmul_rn(xsh[d], xsh[d]));
            x2sh = acc;
        }
        __syncthreads();
        float x2 = x2sh;

        float bestv = 3.4e38f; int besti = 0x7fffffff;
#pragma unroll
        for (int j = 0; j < 4; ++j) {
            int k = tid * 4 + j;
            const float* crow = cb + (size_t)k * DD;
            float dot = 0.f;
            for (int d = 0; d < DD; ++d)
                dot = __fmaf_rn(xsh[d], crow[d], dot);
            float s = __fsub_rn(__fadd_rn(x2, g_c2e[k]), __fmul_rn(2.f, dot));
            if (s < bestv || (s == bestv && k < besti)) { bestv = s; besti = k; }
        }
        bvs[tid] = bestv; bis[tid] = besti;
        __syncthreads();
        if (tid == 0) {
            float bv = 3.4e38f; int bi = 0x7fffffff;
            for (int t = 0; t < 128; ++t) {
                float v = bvs[t]; int k = bis[t];
                if (v < bv || (v == bv && k < bi)) { bv = v; bi = k; }
            }
            g_idx[node] = bi;
        }
        __syncthreads();
    }
}

// ---------------- z_nodes gather: out_z[i] = codebook[idx[i]] ----------------
__global__ void gather_kernel(const float* __restrict__ cb, float* __restrict__ outz) {
    int gid = blockIdx.x * 256 + threadIdx.x;   // over N*32 float4s
    int i = gid >> 5, q = gid & 31;
    int k = g_idx[i];
    ((float4*)outz)[(size_t)i * 32 + q] = ((const float4*)cb)[(size_t)k * 32 + q];
}

// ---------------- per-graph pooling + three tiny matmuls ----------------
__global__ __launch_bounds__(128) void pool_kernel(
    const float* __restrict__ x, const float* __restrict__ causal,
    const float* __restrict__ counter, const float* __restrict__ fcw,
    const float* __restrict__ fcb, float* __restrict__ out)
{
    __shared__ float pv[3][DD];     // pooled_causal, pooled_counter, pooled_x
    __shared__ float wsh[TT][DD];
    int g = blockIdx.x, d = threadIdx.x;

    for (int j = d; j < TT * DD; j += 128) wsh[j / DD][j % DD] = fcw[j];

    int s = g_seg[g], e = g_seg[g + 1];
    float sx = 0.f, sca = 0.f, sco = 0.f;
    for (int i = s; i < e; ++i) {
        int k = g_idx[i];
        sx  += x      [(size_t)i * DD + d];
        sca += causal [(size_t)k * DD + d];
        sco += counter[(size_t)k * DD + d];
    }
    float cnt = (float)(e - s);
    float inv = 1.f / fmaxf(cnt, 1.f);
    float px  = sx * inv;
    float pca = (sx + sca) * inv;
    float pco = sco * inv;

    out[OFF_PCA + (size_t)g * DD + d] = pca;
    out[OFF_PX  + (size_t)g * DD + d] = px;

    pv[0][d] = pca; pv[1][d] = pco; pv[2][d] = px;
    __syncthreads();

    if (d < 3 * TT) {
        int v = d / TT, t = d % TT;
        float acc = fcb[t];
#pragma unroll 8
        for (int q = 0; q < DD; ++q) acc = fmaf(pv[v][q], wsh[t][q], acc);
        out[(size_t)v * (GG * TT) + g * TT + t] = acc;
    }
}

extern "C" void kernel_launch(void* const* d_in, const int* in_sizes, int n_in,
                              void* d_out, int out_size) {
    const float* x        = (const float*)d_in[0];
    const int*   batch    = (const int*)  d_in[1];
    const float* codebook = (const float*)d_in[2];
    const float* causal   = (const float*)d_in[3];
    const float* counter  = (const float*)d_in[4];
    const float* fcw      = (const float*)d_in[5];
    const float* fcb      = (const float*)d_in[6];
    float* out = (float*)d_out;

    seg_kernel<<<(GG + 1 + 255) / 256, 256>>>(batch, NN);
    c2_kernel<<<KK / 8, 256>>>(causal);
    c2emul_kernel<<<(KK + 127) / 128, 128>>>(causal);
    argmin_kernel<<<NN / 64, 256>>>(x, causal);
    refine_kernel<<<1024, 128>>>(x, causal);
    gather_kernel<<<(NN * 32) / 256, 256>>>(codebook, out + OFF_Z);
    pool_kernel<<<GG, 128>>>(x, causal, counter, fcw, fcb, out);
}

// round 5
// speedup vs baseline: 1.4198x; 1.4198x over previous
#include <cuda_runtime.h>

#define NN 262144
#define DD 128
#define KK 512
#define GG 4096
#define TT 10

// output layout (float32, concatenated reference tuple)
#define OFF_CPRE   0
#define OFF_XPRE   (GG * TT)            // counter_pre
#define OFF_YPRE   (2 * GG * TT)
#define OFF_Z      (3 * GG * TT)
#define OFF_PCA    (OFF_Z + (size_t)NN * DD)
#define OFF_PX     (OFF_PCA + (size_t)GG * DD)

#define MARGIN_THRESH 0.03f
#define XPAD 132                         // xs/cs row stride in floats (16B-aligned rows)
#define CSZ  (16 * XPAD)                 // one cs buffer: 16 d-rows x 128 codes (padded)
#define SMEM_ARG ((128 * XPAD + 2 * CSZ) * 4)

__device__ int   g_idx[NN];
__device__ int   g_seg[GG + 1];
__device__ float g_c2[KK];       // fast-path c2
__device__ float g_c2e[KK];      // reference-emulated c2 (sequential fp32, no fma)
__device__ float g_cbT[DD * KK]; // transposed causal codebook for coalesced refine
__device__ int   g_flag[NN];
__device__ int   g_nflag;

// ---------------- segment offsets via binary search (batch is sorted) ----------------
__global__ void seg_kernel(const int* __restrict__ bw, int n) {
    int g = blockIdx.x * blockDim.x + threadIdx.x;
    if (g == 0) g_nflag = 0;
    if (g > GG) return;
    bool is64 = (bw[n - 1] == 0) && (bw[n - 3] == 0);
    int lo = 0, hi = n;
    while (lo < hi) {
        int mid = (lo + hi) >> 1;
        int v = is64 ? bw[2 * mid] : bw[mid];
        if (v < g) lo = mid + 1; else hi = mid;
    }
    g_seg[g] = lo;
}

// ---------------- fast c2 + emulated c2 + transpose, fused ----------------
__global__ void prep_kernel(const float* __restrict__ cc) {
    int k = blockIdx.x * 8 + (threadIdx.x >> 5);
    int lane = threadIdx.x & 31;
    float v[4];
    float s = 0.f;
#pragma unroll
    for (int j = 0; j < 4; ++j) {
        v[j] = cc[k * DD + lane + 32 * j];
        s = fmaf(v[j], v[j], s);
        g_cbT[(lane + 32 * j) * KK + k] = v[j];   // transpose (uncoalesced but tiny)
    }
#pragma unroll
    for (int o = 16; o; o >>= 1) s += __shfl_xor_sync(0xffffffffu, s, o);
    if (lane == 0) g_c2[k] = s;
    // emulated sequential c2: one lane per code, strict order, no fma
    if (lane == 0) {
        const float* r = cc + (size_t)k * DD;
        float acc = 0.f;
        for (int d = 0; d < DD; ++d)
            acc = __fadd_rn(acc, __fmul_rn(r[d], r[d]));
        g_c2e[k] = acc;
    }
}

// ---------------- argmin: 128 nodes x 512 codes, 8x8 register tile ----------------
__global__ __launch_bounds__(256, 2) void argmin_kernel(
    const float* __restrict__ x, const float* __restrict__ cb)
{
    extern __shared__ float sm[];
    float* xs = sm;                      // [128][XPAD] transposed: xs[d*XPAD + n]
    float* cs = sm + 128 * XPAD;         // [2][16][XPAD]: cs[buf*CSZ + dd*XPAD + c]

    const int tid = threadIdx.x;
    const int tx = tid & 15;             // nodes 8*tx .. 8*tx+7
    const int ty = tid >> 4;             // codes 8*ty .. 8*ty+7 (within 128-tile)
    const int nbase = blockIdx.x * 128;
    const float4* cb4 = (const float4*)cb;

    // fill xs transposed: scalar loads, gmem coalesced (lane = consecutive d),
    // STS stride XPAD -> 4-way bank conflict only.
    {
        const int lane = tid & 31;
        const int nw   = tid >> 5;       // warp id: 8 warps
#pragma unroll
        for (int blk = 0; blk < 16; ++blk) {
            int n = nw + 8 * blk;        // node 0..127
#pragma unroll
            for (int dq = 0; dq < 4; ++dq) {
                int d = lane + 32 * dq;
                xs[d * XPAD + n] = x[(size_t)(nbase + n) * DD + d];
            }
        }
    }

    float bestv[8], bestv2[8];
    int   besti[8];
#pragma unroll
    for (int j = 0; j < 8; ++j) { bestv[j] = 3.4e38f; bestv2[j] = 3.4e38f; besti[j] = 0; }

    const int c0 = tid >> 2;             // code row this thread loads (2 iters -> 0..127)
    const int q0 = tid & 3;

    for (int kt = 0; kt < 4; ++kt) {
        float acc[8][8];
#pragma unroll
        for (int j = 0; j < 8; ++j)
#pragma unroll
            for (int i = 0; i < 8; ++i) acc[j][i] = 0.f;

        // preload dc=0 tile
        float4 pre[2];
#pragma unroll
        for (int jj = 0; jj < 2; ++jj) {
            int c = c0 + 64 * jj;
            pre[jj] = cb4[(size_t)(kt * 128 + c) * 32 + q0];
        }
#pragma unroll
        for (int jj = 0; jj < 2; ++jj) {
            int c = c0 + 64 * jj;
            cs[(4 * q0 + 0) * XPAD + c] = pre[jj].x;
            cs[(4 * q0 + 1) * XPAD + c] = pre[jj].y;
            cs[(4 * q0 + 2) * XPAD + c] = pre[jj].z;
            cs[(4 * q0 + 3) * XPAD + c] = pre[jj].w;
        }
        __syncthreads();

        for (int dc = 0; dc < 8; ++dc) {
            const int cur = dc & 1;
            float* csc = cs + cur * CSZ;
            if (dc < 7) {
#pragma unroll
                for (int jj = 0; jj < 2; ++jj) {
                    int c = c0 + 64 * jj;
                    pre[jj] = cb4[(size_t)(kt * 128 + c) * 32 + (dc + 1) * 4 + q0];
                }
            }
#pragma unroll
            for (int dd = 0; dd < 16; ++dd) {
                const int d = dc * 16 + dd;
                float4 a0 = *(const float4*)&xs[d * XPAD + 8 * tx];
                float4 a1 = *(const float4*)&xs[d * XPAD + 8 * tx + 4];
                float4 b0 = *(const float4*)&csc[dd * XPAD + 8 * ty];
                float4 b1 = *(const float4*)&csc[dd * XPAD + 8 * ty + 4];
                float av[8] = {a0.x, a0.y, a0.z, a0.w, a1.x, a1.y, a1.z, a1.w};
                float bv[8] = {b0.x, b0.y, b0.z, b0.w, b1.x, b1.y, b1.z, b1.w};
#pragma unroll
                for (int j = 0; j < 8; ++j)
#pragma unroll
                    for (int i = 0; i < 8; ++i)
                        acc[j][i] = fmaf(av[j], bv[i], acc[j][i]);
            }
            if (dc < 7) {
                float* csn = cs + (cur ^ 1) * CSZ;
#pragma unroll
                for (int jj = 0; jj < 2; ++jj) {
                    int c = c0 + 64 * jj;
                    csn[(4 * q0 + 0) * XPAD + c] = pre[jj].x;
                    csn[(4 * q0 + 1) * XPAD + c] = pre[jj].y;
                    csn[(4 * q0 + 2) * XPAD + c] = pre[jj].z;
                    csn[(4 * q0 + 3) * XPAD + c] = pre[jj].w;
                }
            }
            __syncthreads();
        }

        // fold: score = c2 - 2*dot, top-2 (codes ascending within thread)
#pragma unroll
        for (int i = 0; i < 8; ++i) {
            int k = kt * 128 + 8 * ty + i;
            float c2v = g_c2[k];
#pragma unroll
            for (int j = 0; j < 8; ++j) {
                float s = fmaf(-2.f, acc[j][i], c2v);
                if (s < bestv[j]) { bestv2[j] = bestv[j]; bestv[j] = s; besti[j] = k; }
                else if (s < bestv2[j]) bestv2[j] = s;
            }
        }
    }

    // cross-thread top-2 reduction over 16 ty-groups (scratch overlays xs; all xs
    // reads completed before the final mainloop __syncthreads)
    float* rv  = xs;                      // [16][128]
    float* rv2 = xs + 2048;               // [16][128]
    int*   ri  = (int*)(xs + 4096);       // [16][128]
#pragma unroll
    for (int j = 0; j < 8; ++j) {
        rv [ty * 128 + 8 * tx + j] = bestv[j];
        rv2[ty * 128 + 8 * tx + j] = bestv2[j];
        ri [ty * 128 + 8 * tx + j] = besti[j];
    }
    __syncthreads();
    if (tid < 128) {
        float bv = 3.4e38f, bv2 = 3.4e38f; int bi = 0x7fffffff;
#pragma unroll
        for (int t = 0; t < 16; ++t) {
            float v1 = rv[t * 128 + tid], v2 = rv2[t * 128 + tid];
            int   k1 = ri[t * 128 + tid];
            if (v1 < bv || (v1 == bv && k1 < bi)) {
                bv2 = fminf(bv, v2); bv = v1; bi = k1;
            } else {
                bv2 = fminf(bv2, v1);
            }
        }
        int node = nbase + tid;
        g_idx[node] = bi;
        if (bv2 - bv < MARGIN_THRESH) {
            int pos = atomicAdd(&g_nflag, 1);
            g_flag[pos] = node;
        }
    }
}

// ---------------- near-tie refine: bit-emulate the reference's fp32 arithmetic --------
// d2_ref[k] = fadd(x2, c2e[k]) - 2*dot, dot = k-ascending fmaf chain,
// x2/c2e = strict sequential mul+add. Coalesced via transposed codebook.
__global__ __launch_bounds__(128) void refine_kernel(const float* __restrict__ x)
{
    __shared__ float xsh[DD];
    __shared__ float x2sh;
    __shared__ float bvs[128];
    __shared__ int   bis[128];
    const int tid = threadIdx.x;
    const int nflag = g_nflag;

    for (int f = blockIdx.x; f < nflag; f += gridDim.x) {
        int node = g_flag[f];
        xsh[tid] = x[(size_t)node * DD + tid];
        __syncthreads();
        if (tid == 0) {
            float acc = 0.f;
            for (int d = 0; d < DD; ++d)
                acc = __fadd_rn(acc, __fmul_rn(xsh[d], xsh[d]));
            x2sh = acc;
        }
        __syncthreads();
        float x2 = x2sh;

        float bestv = 3.4e38f; int besti = 0x7fffffff;
#pragma unroll
        for (int j = 0; j < 4; ++j) {
            int k = j * 128 + tid;               // lane-consecutive k: coalesced
            float dot = 0.f;
            for (int d = 0; d < DD; ++d)
                dot = __fmaf_rn(xsh[d], g_cbT[d * KK + k], dot);
            float s = __fsub_rn(__fadd_rn(x2, g_c2e[k]), __fmul_rn(2.f, dot));
            if (s < bestv || (s == bestv && k < besti)) { bestv = s; besti = k; }
        }
        bvs[tid] = bestv; bis[tid] = besti;
        __syncthreads();
        if (tid == 0) {
            float bv = 3.4e38f; int bi = 0x7fffffff;
            for (int t = 0; t < 128; ++t) {
                float v = bvs[t]; int k = bis[t];
                if (v < bv || (v == bv && k < bi)) { bv = v; bi = k; }
            }
            g_idx[node] = bi;
        }
        __syncthreads();
    }
}

// ---------------- z_nodes gather: out_z[i] = codebook[idx[i]] ----------------
__global__ void gather_kernel(const float* __restrict__ cb, float* __restrict__ outz) {
    int gid = blockIdx.x * 256 + threadIdx.x;   // over N*32 float4s
    int i = gid >> 5, q = gid & 31;
    int k = g_idx[i];
    ((float4*)outz)[(size_t)i * 32 + q] = ((const float4*)cb)[(size_t)k * 32 + q];
}

// ---------------- per-graph pooling + three tiny matmuls ----------------
__global__ __launch_bounds__(128) void pool_kernel(
    const float* __restrict__ x, const float* __restrict__ causal,
    const float* __restrict__ counter, const float* __restrict__ fcw,
    const float* __restrict__ fcb, float* __restrict__ out)
{
    __shared__ float pv[3][DD];
    __shared__ float wsh[TT][DD];
    int g = blockIdx.x, d = threadIdx.x;

    for (int j = d; j < TT * DD; j += 128) wsh[j / DD][j % DD] = fcw[j];

    int s = g_seg[g], e = g_seg[g + 1];
    float sx0 = 0.f, sx1 = 0.f, sx2 = 0.f, sx3 = 0.f;
    float sa0 = 0.f, sa1 = 0.f, sa2 = 0.f, sa3 = 0.f;
    float sc0 = 0.f, sc1 = 0.f, sc2 = 0.f, sc3 = 0.f;
    int i = s;
    for (; i + 4 <= e; i += 4) {
        int k0 = g_idx[i], k1 = g_idx[i + 1], k2 = g_idx[i + 2], k3 = g_idx[i + 3];
        sx0 += x[(size_t)(i    ) * DD + d];
        sx1 += x[(size_t)(i + 1) * DD + d];
        sx2 += x[(size_t)(i + 2) * DD + d];
        sx3 += x[(size_t)(i + 3) * DD + d];
        sa0 += causal[(size_t)k0 * DD + d];
        sa1 += causal[(size_t)k1 * DD + d];
        sa2 += causal[(size_t)k2 * DD + d];
        sa3 += causal[(size_t)k3 * DD + d];
        sc0 += counter[(size_t)k0 * DD + d];
        sc1 += counter[(size_t)k1 * DD + d];
        sc2 += counter[(size_t)k2 * DD + d];
        sc3 += counter[(size_t)k3 * DD + d];
    }
    for (; i < e; ++i) {
        int k = g_idx[i];
        sx0 += x[(size_t)i * DD + d];
        sa0 += causal[(size_t)k * DD + d];
        sc0 += counter[(size_t)k * DD + d];
    }
    float sx = (sx0 + sx1) + (sx2 + sx3);
    float sa = (sa0 + sa1) + (sa2 + sa3);
    float sc = (sc0 + sc1) + (sc2 + sc3);

    float cnt = (float)(e - s);
    float inv = 1.f / fmaxf(cnt, 1.f);
    float px  = sx * inv;
    float pca = (sx + sa) * inv;
    float pco = sc * inv;

    out[OFF_PCA + (size_t)g * DD + d] = pca;
    out[OFF_PX  + (size_t)g * DD + d] = px;

    pv[0][d] = pca; pv[1][d] = pco; pv[2][d] = px;
    __syncthreads();

    if (d < 3 * TT) {
        int v = d / TT, t = d % TT;
        float acc = fcb[t];
#pragma unroll 8
        for (int q = 0; q < DD; ++q) acc = fmaf(pv[v][q], wsh[t][q], acc);
        out[(size_t)v * (GG * TT) + g * TT + t] = acc;
    }
}

extern "C" void kernel_launch(void* const* d_in, const int* in_sizes, int n_in,
                              void* d_out, int out_size) {
    const float* x        = (const float*)d_in[0];
    const int*   batch    = (const int*)  d_in[1];
    const float* codebook = (const float*)d_in[2];
    const float* causal   = (const float*)d_in[3];
    const float* counter  = (const float*)d_in[4];
    const float* fcw      = (const float*)d_in[5];
    const float* fcb      = (const float*)d_in[6];
    float* out = (float*)d_out;

    cudaFuncSetAttribute(argmin_kernel,
                         cudaFuncAttributeMaxDynamicSharedMemorySize, SMEM_ARG);

    seg_kernel<<<(GG + 1 + 255) / 256, 256>>>(batch, NN);
    prep_kernel<<<KK / 8, 256>>>(causal);
    argmin_kernel<<<NN / 128, 256, SMEM_ARG>>>(x, causal);
    refine_kernel<<<1024, 128>>>(x);
    gather_kernel<<<(NN * 32) / 256, 256>>>(codebook, out + OFF_Z);
    pool_kernel<<<GG, 128>>>(x, causal, counter, fcw, fcb, out);
}

// round 8
// speedup vs baseline: 2.1774x; 1.5337x over previous
#include <cuda_runtime.h>
#include <cuda_bf16.h>
#include <mma.h>
#include <cstdint>

using namespace nvcuda;

#define NN 262144
#define DD 128
#define KK 512
#define GG 4096
#define TT 10

// output layout (float32, concatenated reference tuple)
#define OFF_CPRE   0
#define OFF_XPRE   (GG * TT)            // counter_pre
#define OFF_YPRE   (2 * GG * TT)
#define OFF_Z      (3 * GG * TT)
#define OFF_PCA    (OFF_Z + (size_t)NN * DD)
#define OFF_PX     (OFF_PCA + (size_t)GG * DD)

#define MARGIN_THRESH 0.01f

#define LDB 136                         // bf16 tile leading dim (elements)
#define LDP 132                         // fp32 score tile leading dim (elements)

// smem byte offsets: [xh][xl][bh][bl][c2]; fp32 score tile ps overlays bh+bl
#define SM_XH   0
#define SM_XL   34816                   // 128*136*2
#define SM_BH   69632
#define SM_BL   104448
#define SM_C2   139264                  // 512 floats
#define SMEM_TC 141312

__device__ int   g_idx[NN];
__device__ int   g_seg[GG + 1];
__device__ float g_c2[KK];       // fast-path c2
__device__ float g_c2e[KK];      // reference-emulated c2 (sequential fp32, no fma)
__device__ float g_cbT[DD * KK]; // transposed causal codebook for coalesced refine
__device__ int   g_flag[NN];
__device__ int   g_nflag;
__device__ float g_x2f[NN];      // emulated x2 per flagged node (by flag position)

// ---------------- segment offsets via binary search (batch is sorted) ----------------
__global__ void seg_kernel(const int* __restrict__ bw, int n) {
    int g = blockIdx.x * blockDim.x + threadIdx.x;
    if (g == 0) g_nflag = 0;
    if (g > GG) return;
    bool is64 = (bw[n - 1] == 0) && (bw[n - 3] == 0);
    int lo = 0, hi = n;
    while (lo < hi) {
        int mid = (lo + hi) >> 1;
        int v = is64 ? bw[2 * mid] : bw[mid];
        if (v < g) lo = mid + 1; else hi = mid;
    }
    g_seg[g] = lo;
}

// ---------------- fast c2 + emulated c2 + transpose, fused ----------------
__global__ void prep_kernel(const float* __restrict__ cc) {
    int k = blockIdx.x * 8 + (threadIdx.x >> 5);
    int lane = threadIdx.x & 31;
    float v[4];
    float s = 0.f;
#pragma unroll
    for (int j = 0; j < 4; ++j) {
        v[j] = cc[k * DD + lane + 32 * j];
        s = fmaf(v[j], v[j], s);
        g_cbT[(lane + 32 * j) * KK + k] = v[j];
    }
#pragma unroll
    for (int o = 16; o; o >>= 1) s += __shfl_xor_sync(0xffffffffu, s, o);
    if (lane == 0) g_c2[k] = s;
    if (lane == 0) {
        const float* r = cc + (size_t)k * DD;
        float acc = 0.f;
        for (int d = 0; d < DD; ++d)
            acc = __fadd_rn(acc, __fmul_rn(r[d], r[d]));
        g_c2e[k] = acc;
    }
}

// load a 128x128 fp32 tile (row stride DD) into bf16 hi/lo smem tiles, row-major ld=LDB
// 256-thread version: 2048 row-chunks, 8 iterations.
__device__ __forceinline__ void fill_split(
    const float* __restrict__ src, __nv_bfloat16* h, __nv_bfloat16* l, int tid)
{
#pragma unroll
    for (int it = 0; it < 8; ++it) {
        int idx = it * 256 + tid;            // 0..2047
        int row = idx >> 4, ch = idx & 15;   // ch = 8-col chunk
        const float4* p = (const float4*)(src + (size_t)row * DD) + ch * 2;
        float4 v0 = p[0], v1 = p[1];
        float f[8] = {v0.x, v0.y, v0.z, v0.w, v1.x, v1.y, v1.z, v1.w};
        uint32_t hp[4], lp[4];
#pragma unroll
        for (int j = 0; j < 4; ++j) {
            __nv_bfloat16 h0 = __float2bfloat16(f[2 * j]);
            __nv_bfloat16 h1 = __float2bfloat16(f[2 * j + 1]);
            __nv_bfloat16 l0 = __float2bfloat16(f[2 * j]     - __bfloat162float(h0));
            __nv_bfloat16 l1 = __float2bfloat16(f[2 * j + 1] - __bfloat162float(h1));
            hp[j] = ((uint32_t)__bfloat16_as_ushort(h1) << 16) | __bfloat16_as_ushort(h0);
            lp[j] = ((uint32_t)__bfloat16_as_ushort(l1) << 16) | __bfloat16_as_ushort(l0);
        }
        int eo = row * LDB + ch * 8;         // element offset; byte = 2*eo (16B aligned)
        *(uint4*)((char*)h + 2 * eo) = make_uint4(hp[0], hp[1], hp[2], hp[3]);
        *(uint4*)((char*)l + 2 * eo) = make_uint4(lp[0], lp[1], lp[2], lp[3]);
    }
}

// ---------------- HMMA argmin: 128 nodes/CTA, split-bf16 3-pass, wmma ----------------
__global__ __launch_bounds__(256) void argmin_tc(
    const float* __restrict__ x, const float* __restrict__ cb)
{
    extern __shared__ char smem[];
    __nv_bfloat16* xh = (__nv_bfloat16*)(smem + SM_XH);
    __nv_bfloat16* xl = (__nv_bfloat16*)(smem + SM_XL);
    __nv_bfloat16* bh = (__nv_bfloat16*)(smem + SM_BH);
    __nv_bfloat16* bl = (__nv_bfloat16*)(smem + SM_BL);
    float*         c2s = (float*)(smem + SM_C2);
    float*         ps  = (float*)(smem + SM_BH);   // overlays bh/bl after mma

    const int tid = threadIdx.x;
    const int wid = tid >> 5;
    const int wm  = wid & 3;             // row block: nodes 32*wm..32*wm+31
    const int wn  = wid >> 2;            // col block: codes 64*wn..64*wn+63
    const int nbase = blockIdx.x * 128;

    fill_split(x + (size_t)nbase * DD, xh, xl, tid);
    for (int k = tid; k < KK; k += 256) c2s[k] = g_c2[k];
    __syncthreads();

    float bestv = 3.4e38f, bestv2 = 3.4e38f;
    int   besti = 0;

    for (int kt = 0; kt < 4; ++kt) {
        fill_split(cb + (size_t)(kt * 128) * DD, bh, bl, tid);
        __syncthreads();

        wmma::fragment<wmma::accumulator, 16, 16, 16, float> acc[2][4];
#pragma unroll
        for (int i = 0; i < 2; ++i)
#pragma unroll
            for (int j = 0; j < 4; ++j) wmma::fill_fragment(acc[i][j], 0.f);

#pragma unroll
        for (int kk = 0; kk < 8; ++kk) {
            const int k0 = kk * 16;
            wmma::fragment<wmma::matrix_a, 16, 16, 16, __nv_bfloat16, wmma::row_major> ah[2], al[2];
            wmma::fragment<wmma::matrix_b, 16, 16, 16, __nv_bfloat16, wmma::col_major> bhf[4], blf[4];
#pragma unroll
            for (int i = 0; i < 2; ++i) {
                wmma::load_matrix_sync(ah[i], xh + (wm * 32 + i * 16) * LDB + k0, LDB);
                wmma::load_matrix_sync(al[i], xl + (wm * 32 + i * 16) * LDB + k0, LDB);
            }
#pragma unroll
            for (int j = 0; j < 4; ++j) {
                wmma::load_matrix_sync(bhf[j], bh + (wn * 64 + j * 16) * LDB + k0, LDB);
                wmma::load_matrix_sync(blf[j], bl + (wn * 64 + j * 16) * LDB + k0, LDB);
            }
#pragma unroll
            for (int i = 0; i < 2; ++i)
#pragma unroll
                for (int j = 0; j < 4; ++j) {
                    wmma::mma_sync(acc[i][j], ah[i], bhf[j], acc[i][j]);
                    wmma::mma_sync(acc[i][j], ah[i], blf[j], acc[i][j]);
                    wmma::mma_sync(acc[i][j], al[i], bhf[j], acc[i][j]);
                }
        }
        __syncthreads();   // all warps done reading bh/bl -> safe to overwrite with ps

#pragma unroll
        for (int i = 0; i < 2; ++i)
#pragma unroll
            for (int j = 0; j < 4; ++j)
                wmma::store_matrix_sync(
                    ps + (wm * 32 + i * 16) * LDP + wn * 64 + j * 16,
                    acc[i][j], LDP, wmma::mem_row_major);
        __syncthreads();

        // per-node scan of 128 codes (k ascending: first-min tie-break preserved)
        if (tid < 128) {
            const float4* row = (const float4*)(ps + tid * LDP);
#pragma unroll
            for (int q = 0; q < 32; ++q) {
                float4 v = row[q];
                float d4[4] = {v.x, v.y, v.z, v.w};
#pragma unroll
                for (int u = 0; u < 4; ++u) {
                    int k = kt * 128 + 4 * q + u;
                    float s = fmaf(-2.f, d4[u], c2s[k]);
                    if (s < bestv)       { bestv2 = bestv; bestv = s; besti = k; }
                    else if (s < bestv2) { bestv2 = s; }
                }
            }
        }
        __syncthreads();   // scan done before next tile overwrites bh/bl
    }

    if (tid < 128) {
        int node = nbase + tid;
        g_idx[node] = besti;
        if (bestv2 - bestv < MARGIN_THRESH) {
            int pos = atomicAdd(&g_nflag, 1);
            g_flag[pos] = node;
        }
    }
}

// ---------------- emulated x2 for flagged nodes (parallel, one thread/node) ----------
__global__ void x2pre_kernel(const float* __restrict__ x) {
    int nf = g_nflag;
    for (int j = blockIdx.x * 128 + threadIdx.x; j < nf; j += gridDim.x * 128) {
        const float* r = x + (size_t)g_flag[j] * DD;
        float acc = 0.f;
        for (int d = 0; d < DD; ++d)
            acc = __fadd_rn(acc, __fmul_rn(r[d], r[d]));
        g_x2f[j] = acc;
    }
}

// ---------------- near-tie refine: bit-emulate the reference's fp32 arithmetic --------
__global__ __launch_bounds__(128) void refine_kernel(const float* __restrict__ x)
{
    __shared__ float xsh[DD];
    __shared__ float bvs[128];
    __shared__ int   bis[128];
    const int tid = threadIdx.x;
    const int nflag = g_nflag;

    for (int f = blockIdx.x; f < nflag; f += gridDim.x) {
        int node = g_flag[f];
        xsh[tid] = x[(size_t)node * DD + tid];
        __syncthreads();
        float x2 = g_x2f[f];

        float bestv = 3.4e38f; int besti = 0x7fffffff;
#pragma unroll
        for (int j = 0; j < 4; ++j) {
            int k = j * 128 + tid;               // lane-consecutive k: coalesced
            float dot = 0.f;
            for (int d = 0; d < DD; ++d)
                dot = __fmaf_rn(xsh[d], g_cbT[d * KK + k], dot);
            float s = __fsub_rn(__fadd_rn(x2, g_c2e[k]), __fmul_rn(2.f, dot));
            if (s < bestv || (s == bestv && k < besti)) { bestv = s; besti = k; }
        }
        bvs[tid] = bestv; bis[tid] = besti;
        __syncthreads();
        for (int st = 64; st > 0; st >>= 1) {
            if (tid < st) {
                float v2 = bvs[tid + st]; int k2 = bis[tid + st];
                if (v2 < bvs[tid] || (v2 == bvs[tid] && k2 < bis[tid])) {
                    bvs[tid] = v2; bis[tid] = k2;
                }
            }
            __syncthreads();
        }
        if (tid == 0) g_idx[node] = bis[0];
        __syncthreads();
    }
}

// ---------------- z_nodes gather: out_z[i] = codebook[idx[i]] ----------------
__global__ void gather_kernel(const float* __restrict__ cb, float* __restrict__ outz) {
    int gid = blockIdx.x * 256 + threadIdx.x;   // over N*32 float4s
    int i = gid >> 5, q = gid & 31;
    int k = g_idx[i];
    ((float4*)outz)[(size_t)i * 32 + q] = ((const float4*)cb)[(size_t)k * 32 + q];
}

// ---------------- per-graph pooling + three tiny matmuls (32 threads, float4) --------
__global__ __launch_bounds__(32) void pool_kernel(
    const float* __restrict__ x, const float* __restrict__ causal,
    const float* __restrict__ counter, const float* __restrict__ fcw,
    const float* __restrict__ fcb, float* __restrict__ out)
{
    __shared__ float pv[3][DD];
    __shared__ float wsh[TT][DD];
    const int g = blockIdx.x, t = threadIdx.x;   // t in [0,32)

    for (int j = t; j < TT * DD; j += 32) wsh[j / DD][j % DD] = fcw[j];

    const float4* x4 = (const float4*)x;
    const float4* a4 = (const float4*)causal;
    const float4* c4 = (const float4*)counter;

    int s = g_seg[g], e = g_seg[g + 1];
    float4 sx0 = {0,0,0,0}, sx1 = {0,0,0,0};
    float4 sa0 = {0,0,0,0}, sa1 = {0,0,0,0};
    float4 sc0 = {0,0,0,0}, sc1 = {0,0,0,0};
    int i = s;
    for (; i + 2 <= e; i += 2) {
        int k0 = g_idx[i], k1 = g_idx[i + 1];
        float4 vx0 = x4[(size_t)(i    ) * 32 + t];
        float4 vx1 = x4[(size_t)(i + 1) * 32 + t];
        float4 va0 = a4[(size_t)k0 * 32 + t];
        float4 va1 = a4[(size_t)k1 * 32 + t];
        float4 vc0 = c4[(size_t)k0 * 32 + t];
        float4 vc1 = c4[(size_t)k1 * 32 + t];
        sx0.x += vx0.x; sx0.y += vx0.y; sx0.z += vx0.z; sx0.w += vx0.w;
        sx1.x += vx1.x; sx1.y += vx1.y; sx1.z += vx1.z; sx1.w += vx1.w;
        sa0.x += va0.x; sa0.y += va0.y; sa0.z += va0.z; sa0.w += va0.w;
        sa1.x += va1.x; sa1.y += va1.y; sa1.z += va1.z; sa1.w += va1.w;
        sc0.x += vc0.x; sc0.y += vc0.y; sc0.z += vc0.z; sc0.w += vc0.w;
        sc1.x += vc1.x; sc1.y += vc1.y; sc1.z += vc1.z; sc1.w += vc1.w;
    }
    for (; i < e; ++i) {
        int k = g_idx[i];
        float4 vx = x4[(size_t)i * 32 + t];
        float4 va = a4[(size_t)k * 32 + t];
        float4 vc = c4[(size_t)k * 32 + t];
        sx0.x += vx.x; sx0.y += vx.y; sx0.z += vx.z; sx0.w += vx.w;
        sa0.x += va.x; sa0.y += va.y; sa0.z += va.z; sa0.w += va.w;
        sc0.x += vc.x; sc0.y += vc.y; sc0.z += vc.z; sc0.w += vc.w;
    }
    float cnt = (float)(e - s);
    float inv = 1.f / fmaxf(cnt, 1.f);
    float4 px, pca, pco;
    px.x  = (sx0.x + sx1.x) * inv;  px.y  = (sx0.y + sx1.y) * inv;
    px.z  = (sx0.z + sx1.z) * inv;  px.w  = (sx0.w + sx1.w) * inv;
    pca.x = ((sx0.x + sx1.x) + (sa0.x + sa1.x)) * inv;
    pca.y = ((sx0.y + sx1.y) + (sa0.y + sa1.y)) * inv;
    pca.z = ((sx0.z + sx1.z) + (sa0.z + sa1.z)) * inv;
    pca.w = ((sx0.w + sx1.w) + (sa0.w + sa1.w)) * inv;
    pco.x = (sc0.x + sc1.x) * inv;  pco.y = (sc0.y + sc1.y) * inv;
    pco.z = (sc0.z + sc1.z) * inv;  pco.w = (sc0.w + sc1.w) * inv;

    ((float4*)(out + OFF_PCA + (size_t)g * DD))[t] = pca;
    ((float4*)(out + OFF_PX  + (size_t)g * DD))[t] = px;

    ((float4*)pv[0])[t] = pca;
    ((float4*)pv[1])[t] = pco;
    ((float4*)pv[2])[t] = px;
    __syncthreads();

    if (t < 30) {
        int v = t / TT, tk = t % TT;
        float acc = fcb[tk];
#pragma unroll 8
        for (int q = 0; q < DD; ++q) acc = fmaf(pv[v][q], wsh[tk][q], acc);
        out[(size_t)v * (GG * TT) + g * TT + tk] = acc;
    }
}

extern "C" void kernel_launch(void* const* d_in, const int* in_sizes, int n_in,
                              void* d_out, int out_size) {
    const float* x        = (const float*)d_in[0];
    const int*   batch    = (const int*)  d_in[1];
    const float* codebook = (const float*)d_in[2];
    const float* causal   = (const float*)d_in[3];
    const float* counter  = (const float*)d_in[4];
    const float* fcw      = (const float*)d_in[5];
    const float* fcb      = (const float*)d_in[6];
    float* out = (float*)d_out;

    cudaFuncSetAttribute(argmin_tc,
                         cudaFuncAttributeMaxDynamicSharedMemorySize, SMEM_TC);

    seg_kernel<<<(GG + 1 + 255) / 256, 256>>>(batch, NN);
    prep_kernel<<<KK / 8, 256>>>(causal);
    argmin_tc<<<NN / 128, 256, SMEM_TC>>>(x, causal);
    x2pre_kernel<<<64, 128>>>(x);
    refine_kernel<<<256, 128>>>(x);
    gather_kernel<<<(NN * 32) / 256, 256>>>(codebook, out + OFF_Z);
    pool_kernel<<<GG, 32>>>(x, causal, counter, fcw, fcb, out);
}

// round 9
// speedup vs baseline: 2.4635x; 1.1314x over previous
#include <cuda_runtime.h>
#include <cuda_bf16.h>
#include <mma.h>
#include <cstdint>

using namespace nvcuda;

#define NN 262144
#define DD 128
#define KK 512
#define GG 4096
#define TT 10

// output layout (float32, concatenated reference tuple)
#define OFF_CPRE   0
#define OFF_XPRE   (GG * TT)            // counter_pre
#define OFF_YPRE   (2 * GG * TT)
#define OFF_Z      (3 * GG * TT)
#define OFF_PCA    (OFF_Z + (size_t)NN * DD)
#define OFF_PX     (OFF_PCA + (size_t)GG * DD)

#define MARGIN_THRESH 0.01f

#define LDB 136                         // bf16 tile leading dim (elements)
#define LDP 132                         // fp32 score tile leading dim (elements)

#define BTILE_BYTES 69632               // one code tile: bh (34816) + bl (34816)
#define BTILE_U4    4352                // BTILE_BYTES / 16

// smem byte offsets: [xh|xl][B0][B1][c2]; ps overlays the consumed B buffer
#define SM_XH   0
#define SM_XL   34816
#define SM_B0   69632
#define SM_B1   139264
#define SM_C2   208896
#define SMEM_TC 210944

__device__ int   g_idx[NN];
__device__ int   g_seg[GG + 1];
__device__ float g_c2[KK];       // fast-path c2
__device__ float g_c2e[KK];      // reference-emulated c2 (sequential fp32, no fma)
__device__ float g_cbT[DD * KK]; // transposed causal codebook for coalesced refine
__device__ int   g_flag[NN];
__device__ int   g_nflag;
__device__ float g_x2f[NN];      // emulated x2 per flagged node (by flag position)
__device__ uint4 g_cbs[4][BTILE_U4];   // pre-split codebook tiles: [bh | bl] blocked layout

// ---------------- cp.async helpers ----------------
__device__ __forceinline__ void cpa16(uint32_t saddr, const void* gptr) {
    asm volatile("cp.async.cg.shared.global [%0], [%1], 16;"
                 :: "r"(saddr), "l"(gptr));
}
__device__ __forceinline__ void cpa_commit() {
    asm volatile("cp.async.commit_group;");
}
__device__ __forceinline__ void cpa_wait0() {
    asm volatile("cp.async.wait_group 0;");
}

// ---------------- segment offsets via binary search (batch is sorted) ----------------
__global__ void seg_kernel(const int* __restrict__ bw, int n) {
    int g = blockIdx.x * blockDim.x + threadIdx.x;
    if (g == 0) g_nflag = 0;
    if (g > GG) return;
    bool is64 = (bw[n - 1] == 0) && (bw[n - 3] == 0);
    int lo = 0, hi = n;
    while (lo < hi) {
        int mid = (lo + hi) >> 1;
        int v = is64 ? bw[2 * mid] : bw[mid];
        if (v < g) lo = mid + 1; else hi = mid;
    }
    g_seg[g] = lo;
}

// ---------------- fast c2 + emulated c2 + transpose, fused ----------------
__global__ void prep_kernel(const float* __restrict__ cc) {
    int k = blockIdx.x * 8 + (threadIdx.x >> 5);
    int lane = threadIdx.x & 31;
    float v[4];
    float s = 0.f;
#pragma unroll
    for (int j = 0; j < 4; ++j) {
        v[j] = cc[k * DD + lane + 32 * j];
        s = fmaf(v[j], v[j], s);
        g_cbT[(lane + 32 * j) * KK + k] = v[j];
    }
#pragma unroll
    for (int o = 16; o; o >>= 1) s += __shfl_xor_sync(0xffffffffu, s, o);
    if (lane == 0) g_c2[k] = s;
    if (lane == 0) {
        const float* r = cc + (size_t)k * DD;
        float acc = 0.f;
        for (int d = 0; d < DD; ++d)
            acc = __fadd_rn(acc, __fmul_rn(r[d], r[d]));
        g_c2e[k] = acc;
    }
}

// split one 8-float chunk to packed bf16 hi/lo uint4s
__device__ __forceinline__ void split8(const float* f, uint4& H, uint4& L) {
    uint32_t hp[4], lp[4];
#pragma unroll
    for (int j = 0; j < 4; ++j) {
        __nv_bfloat16 h0 = __float2bfloat16(f[2 * j]);
        __nv_bfloat16 h1 = __float2bfloat16(f[2 * j + 1]);
        __nv_bfloat16 l0 = __float2bfloat16(f[2 * j]     - __bfloat162float(h0));
        __nv_bfloat16 l1 = __float2bfloat16(f[2 * j + 1] - __bfloat162float(h1));
        hp[j] = ((uint32_t)__bfloat16_as_ushort(h1) << 16) | __bfloat16_as_ushort(h0);
        lp[j] = ((uint32_t)__bfloat16_as_ushort(l1) << 16) | __bfloat16_as_ushort(l0);
    }
    H = make_uint4(hp[0], hp[1], hp[2], hp[3]);
    L = make_uint4(lp[0], lp[1], lp[2], lp[3]);
}

// ---------------- pre-split codebook tiles to gmem (blocked smem layout) ----------
__global__ __launch_bounds__(256) void prep_split_kernel(const float* __restrict__ cb) {
    const int kt = blockIdx.x;           // 4 tiles
    const int tid = threadIdx.x;
#pragma unroll
    for (int it = 0; it < 8; ++it) {
        int idx = it * 256 + tid;        // 0..2047
        int row = idx >> 4, ch = idx & 15;
        float f[8];
        const float4* p = (const float4*)(cb + (size_t)(kt * 128 + row) * DD) + ch * 2;
        float4 v0 = p[0], v1 = p[1];
        f[0]=v0.x; f[1]=v0.y; f[2]=v0.z; f[3]=v0.w; f[4]=v1.x; f[5]=v1.y; f[6]=v1.z; f[7]=v1.w;
        uint4 H, L;
        split8(f, H, L);
        int u4 = row * 17 + ch;          // 272B rows = 17 uint4; pad word unused
        g_cbs[kt][u4] = H;
        g_cbs[kt][2176 + u4] = L;
    }
}

// load a 128x128 fp32 tile into bf16 hi/lo smem tiles, row-major ld=LDB (256 threads)
__device__ __forceinline__ void fill_split(
    const float* __restrict__ src, __nv_bfloat16* h, __nv_bfloat16* l, int tid)
{
#pragma unroll
    for (int it = 0; it < 8; ++it) {
        int idx = it * 256 + tid;            // 0..2047
        int row = idx >> 4, ch = idx & 15;
        const float4* p = (const float4*)(src + (size_t)row * DD) + ch * 2;
        float4 v0 = p[0], v1 = p[1];
        float f[8] = {v0.x, v0.y, v0.z, v0.w, v1.x, v1.y, v1.z, v1.w};
        uint4 H, L;
        split8(f, H, L);
        int eo = row * LDB + ch * 8;
        *(uint4*)((char*)h + 2 * eo) = H;
        *(uint4*)((char*)l + 2 * eo) = L;
    }
}

// ---------------- HMMA argmin: 128 nodes/CTA, split-bf16 3-pass, cp.async pipeline ---
__global__ __launch_bounds__(256) void argmin_tc(
    const float* __restrict__ x)
{
    extern __shared__ char smem[];
    __nv_bfloat16* xh  = (__nv_bfloat16*)(smem + SM_XH);
    __nv_bfloat16* xl  = (__nv_bfloat16*)(smem + SM_XL);
    float*         c2s = (float*)(smem + SM_C2);

    const int tid = threadIdx.x;
    const int wid = tid >> 5;
    const int wm  = wid & 3;             // row block: nodes 32*wm..
    const int wn  = wid >> 2;            // col block: codes 64*wn..
    const int nbase = blockIdx.x * 128;

    const uint32_t sb0 = (uint32_t)__cvta_generic_to_shared(smem + SM_B0);
    const uint32_t sb1 = (uint32_t)__cvta_generic_to_shared(smem + SM_B1);

    // prefetch tile 0 into B0 while we convert X
    {
        const uint4* src = g_cbs[0];
#pragma unroll
        for (int i = 0; i < 17; ++i) {
            int idx = tid + 256 * i;
            cpa16(sb0 + idx * 16, src + idx);
        }
        cpa_commit();
    }

    fill_split(x + (size_t)nbase * DD, xh, xl, tid);
    for (int k = tid; k < KK; k += 256) c2s[k] = g_c2[k];

    float bestv = 3.4e38f, bestv2 = 3.4e38f;
    int   besti = 0;

    for (int kt = 0; kt < 4; ++kt) {
        cpa_wait0();
        __syncthreads();                 // B tile kt ready (and ps scan of kt-1 done)

        if (kt < 3) {                    // prefetch next tile into the other buffer
            const uint4* src = g_cbs[kt + 1];
            uint32_t dst = ((kt + 1) & 1) ? sb1 : sb0;
#pragma unroll
            for (int i = 0; i < 17; ++i) {
                int idx = tid + 256 * i;
                cpa16(dst + idx * 16, src + idx);
            }
            cpa_commit();
        }

        char* bbase = smem + ((kt & 1) ? SM_B1 : SM_B0);
        __nv_bfloat16* bh = (__nv_bfloat16*)bbase;
        __nv_bfloat16* bl = (__nv_bfloat16*)(bbase + 34816);
        float*         ps = (float*)bbase;

        wmma::fragment<wmma::accumulator, 16, 16, 16, float> acc[2][4];
#pragma unroll
        for (int i = 0; i < 2; ++i)
#pragma unroll
            for (int j = 0; j < 4; ++j) wmma::fill_fragment(acc[i][j], 0.f);

#pragma unroll
        for (int kk = 0; kk < 8; ++kk) {
            const int k0 = kk * 16;
            wmma::fragment<wmma::matrix_a, 16, 16, 16, __nv_bfloat16, wmma::row_major> ah[2], al[2];
            wmma::fragment<wmma::matrix_b, 16, 16, 16, __nv_bfloat16, wmma::col_major> bhf[4], blf[4];
#pragma unroll
            for (int i = 0; i < 2; ++i) {
                wmma::load_matrix_sync(ah[i], xh + (wm * 32 + i * 16) * LDB + k0, LDB);
                wmma::load_matrix_sync(al[i], xl + (wm * 32 + i * 16) * LDB + k0, LDB);
            }
#pragma unroll
            for (int j = 0; j < 4; ++j) {
                wmma::load_matrix_sync(bhf[j], bh + (wn * 64 + j * 16) * LDB + k0, LDB);
                wmma::load_matrix_sync(blf[j], bl + (wn * 64 + j * 16) * LDB + k0, LDB);
            }
#pragma unroll
            for (int i = 0; i < 2; ++i)
#pragma unroll
                for (int j = 0; j < 4; ++j) {
                    wmma::mma_sync(acc[i][j], ah[i], bhf[j], acc[i][j]);
                    wmma::mma_sync(acc[i][j], ah[i], blf[j], acc[i][j]);
                    wmma::mma_sync(acc[i][j], al[i], bhf[j], acc[i][j]);
                }
        }
        __syncthreads();                 // all warps done reading bh/bl

#pragma unroll
        for (int i = 0; i < 2; ++i)
#pragma unroll
            for (int j = 0; j < 4; ++j)
                wmma::store_matrix_sync(
                    ps + (wm * 32 + i * 16) * LDP + wn * 64 + j * 16,
                    acc[i][j], LDP, wmma::mem_row_major);
        __syncthreads();

        // per-node scan of 128 codes (k ascending: first-min tie-break preserved)
        if (tid < 128) {
            const float4* row = (const float4*)(ps + tid * LDP);
#pragma unroll
            for (int q = 0; q < 32; ++q) {
                float4 v = row[q];
                float d4[4] = {v.x, v.y, v.z, v.w};
#pragma unroll
                for (int u = 0; u < 4; ++u) {
                    int k = kt * 128 + 4 * q + u;
                    float s = fmaf(-2.f, d4[u], c2s[k]);
                    if (s < bestv)       { bestv2 = bestv; bestv = s; besti = k; }
                    else if (s < bestv2) { bestv2 = s; }
                }
            }
        }
        __syncthreads();                 // scan done before ps region reused
    }

    if (tid < 128) {
        int node = nbase + tid;
        g_idx[node] = besti;
        if (bestv2 - bestv < MARGIN_THRESH) {
            int pos = atomicAdd(&g_nflag, 1);
            g_flag[pos] = node;
        }
    }
}

// ---------------- emulated x2 for flagged nodes (parallel, one thread/node) ----------
__global__ void x2pre_kernel(const float* __restrict__ x) {
    int nf = g_nflag;
    for (int j = blockIdx.x * 128 + threadIdx.x; j < nf; j += gridDim.x * 128) {
        const float* r = x + (size_t)g_flag[j] * DD;
        float acc = 0.f;
        for (int d = 0; d < DD; ++d)
            acc = __fadd_rn(acc, __fmul_rn(r[d], r[d]));
        g_x2f[j] = acc;
    }
}

// ---------------- near-tie refine: bit-emulate the reference's fp32 arithmetic --------
__global__ __launch_bounds__(128) void refine_kernel(const float* __restrict__ x)
{
    __shared__ float xsh[DD];
    __shared__ float bvs[128];
    __shared__ int   bis[128];
    const int tid = threadIdx.x;
    const int nflag = g_nflag;

    for (int f = blockIdx.x; f < nflag; f += gridDim.x) {
        int node = g_flag[f];
        xsh[tid] = x[(size_t)node * DD + tid];
        __syncthreads();
        float x2 = g_x2f[f];

        float bestv = 3.4e38f; int besti = 0x7fffffff;
#pragma unroll
        for (int j = 0; j < 4; ++j) {
            int k = j * 128 + tid;               // lane-consecutive k: coalesced
            float dot = 0.f;
            for (int d = 0; d < DD; ++d)
                dot = __fmaf_rn(xsh[d], g_cbT[d * KK + k], dot);
            float s = __fsub_rn(__fadd_rn(x2, g_c2e[k]), __fmul_rn(2.f, dot));
            if (s < bestv || (s == bestv && k < besti)) { bestv = s; besti = k; }
        }
        bvs[tid] = bestv; bis[tid] = besti;
        __syncthreads();
        for (int st = 64; st > 0; st >>= 1) {
            if (tid < st) {
                float v2 = bvs[tid + st]; int k2 = bis[tid + st];
                if (v2 < bvs[tid] || (v2 == bvs[tid] && k2 < bis[tid])) {
                    bvs[tid] = v2; bis[tid] = k2;
                }
            }
            __syncthreads();
        }
        if (tid == 0) g_idx[node] = bis[0];
        __syncthreads();
    }
}

// ---------------- z_nodes gather: out_z[i] = codebook[idx[i]] ----------------
__global__ void gather_kernel(const float* __restrict__ cb, float* __restrict__ outz) {
    int gid = blockIdx.x * 256 + threadIdx.x;   // over N*32 float4s
    int i = gid >> 5, q = gid & 31;
    int k = g_idx[i];
    ((float4*)outz)[(size_t)i * 32 + q] = ((const float4*)cb)[(size_t)k * 32 + q];
}

// ---------------- per-graph pooling + tiny matmuls (128 threads, 4-warp split) -------
__global__ __launch_bounds__(128) void pool_kernel(
    const float* __restrict__ x, const float* __restrict__ causal,
    const float* __restrict__ counter, const float* __restrict__ fcw,
    const float* __restrict__ fcb, float* __restrict__ out)
{
    __shared__ float part[4][3][DD];   // per-warp partial sums
    __shared__ float pv[3][DD];
    __shared__ float wsh[TT * DD];
    const int g = blockIdx.x, tid = threadIdx.x;
    const int w = tid >> 5, t = tid & 31;

    for (int j = tid; j < TT * DD; j += 128) wsh[j] = fcw[j];

    const float4* x4 = (const float4*)x;
    const float4* a4 = (const float4*)causal;
    const float4* c4 = (const float4*)counter;

    int s = g_seg[g], e = g_seg[g + 1];
    float4 sx = {0,0,0,0}, sa = {0,0,0,0}, sc = {0,0,0,0};
#pragma unroll 2
    for (int i = s + w; i < e; i += 4) {
        int k = g_idx[i];
        float4 vx = x4[(size_t)i * 32 + t];
        float4 va = a4[(size_t)k * 32 + t];
        float4 vc = c4[(size_t)k * 32 + t];
        sx.x += vx.x; sx.y += vx.y; sx.z += vx.z; sx.w += vx.w;
        sa.x += va.x; sa.y += va.y; sa.z += va.z; sa.w += va.w;
        sc.x += vc.x; sc.y += vc.y; sc.z += vc.z; sc.w += vc.w;
    }
    ((float4*)part[w][0])[t] = sx;
    ((float4*)part[w][1])[t] = sa;
    ((float4*)part[w][2])[t] = sc;
    __syncthreads();

    // combine: thread tid owns dimension d = tid
    float fx = (part[0][0][tid] + part[1][0][tid]) + (part[2][0][tid] + part[3][0][tid]);
    float fa = (part[0][1][tid] + part[1][1][tid]) + (part[2][1][tid] + part[3][1][tid]);
    float fc = (part[0][2][tid] + part[1][2][tid]) + (part[2][2][tid] + part[3][2][tid]);

    float cnt = (float)(e - s);
    float inv = 1.f / fmaxf(cnt, 1.f);
    float px  = fx * inv;
    float pca = (fx + fa) * inv;
    float pco = fc * inv;

    out[OFF_PCA + (size_t)g * DD + tid] = pca;
    out[OFF_PX  + (size_t)g * DD + tid] = px;

    pv[0][tid] = pca; pv[1][tid] = pco; pv[2][tid] = px;
    __syncthreads();

    if (tid < 3 * TT) {
        int v = tid / TT, tk = tid % TT;
        float acc = fcb[tk];
#pragma unroll 8
        for (int q = 0; q < DD; ++q) acc = fmaf(pv[v][q], wsh[tk * DD + q], acc);
        out[(size_t)v * (GG * TT) + g * TT + tk] = acc;
    }
}

extern "C" void kernel_launch(void* const* d_in, const int* in_sizes, int n_in,
                              void* d_out, int out_size) {
    const float* x        = (const float*)d_in[0];
    const int*   batch    = (const int*)  d_in[1];
    const float* codebook = (const float*)d_in[2];
    const float* causal   = (const float*)d_in[3];
    const float* counter  = (const float*)d_in[4];
    const float* fcw      = (const float*)d_in[5];
    const float* fcb      = (const float*)d_in[6];
    float* out = (float*)d_out;

    cudaFuncSetAttribute(argmin_tc,
                         cudaFuncAttributeMaxDynamicSharedMemorySize, SMEM_TC);

    seg_kernel<<<(GG + 1 + 255) / 256, 256>>>(batch, NN);
    prep_kernel<<<KK / 8, 256>>>(causal);
    prep_split_kernel<<<4, 256>>>(causal);
    argmin_tc<<<NN / 128, 256, SMEM_TC>>>(x);
    x2pre_kernel<<<256, 128>>>(x);
    refine_kernel<<<256, 128>>>(x);
    gather_kernel<<<(NN * 32) / 256, 256>>>(codebook, out + OFF_Z);
    pool_kernel<<<GG, 128>>>(x, causal, counter, fcw, fcb, out);
}